// round 3
// baseline (speedup 1.0000x reference)
#include <cuda_runtime.h>
#include <cuda_bf16.h>

// Fused gamma-pdf-weighted MSE mean reduction — single kernel, last-block-done.
// mean( 0.5*(output-target)^2 * ef(target) )
// ef(y) = (BETA - c)*(1 - pdf(y)/FX_MAX) + c,  c = 1/(Y_MAX - Y_MIN)
//
// pdf/FX_MAX = exp( (a-1)*ln(x) - x + C0 ),  x = (y - loc)/scale
// For fp32 uniform targets pdf/FX_MAX < 4e-19 except at exact zeros, so the
// log/exp runs only in a cold branch (y < 1e-6) — hot loop has no MUFU.
//
// Correctness-of-synchronization notes (R2 hang post-mortem):
//  * every __shfl_down_sync runs in a fully-active warp (mask == active set)
//  * arrival counter via atomicInc(&c, NBLK-1): wraps to 0 on the last block,
//    so it self-resets atomically for CUDA-graph replay (no plain-store race)
//  * release fence (writer) before atomicInc; acquire fence (last block)
//    after observing the final count, before reading g_part
//  * final reduce is fixed-order -> deterministic output

#define NBLK 1184   // 148 SMs * 8 = exactly one wave at 256 thr / 8 blocks per SM
#define NTH  256

__device__ float        g_part[NBLK];
__device__ unsigned int g_count;   // zero-init at module load; self-resetting

__device__ __forceinline__ float elem_val(float o, float y) {
    const float A1        = -0.9355570857535674f;            // EST_A - 1
    const float NEG_LOC   = 1.1328205299926424e-27f;         // -EST_LOC
    const float INV_SCALE = (float)(1.0 / 1.5376362609160314);
    const float C0        = -58.4492351f;                    // -lgamma(a)-ln(scale)-ln(FX_MAX)
    const float C         = (float)(1.0 / 107.2185);         // 1/(Y_MAX - Y_MIN)
    const float BC        = 5.0f - (float)(1.0 / 107.2185);  // BETA - c

    float r = 0.0f;
    if (y < 1e-6f) {                      // cold path: only (near-)zero targets
        float x  = (y + NEG_LOC) * INV_SCALE;
        float lp = fmaf(A1, __logf(x), C0) - x;
        r = __expf(lp);                   // = pdf/FX_MAX
    }
    float ef   = fmaf(BC, 1.0f - r, C);   // (BETA-c)*(1-r) + c
    float diff = o - y;
    return 0.5f * diff * diff * ef;
}

__global__ __launch_bounds__(NTH) void loss_fused_kernel(
    const float* __restrict__ out, const float* __restrict__ tgt,
    float* __restrict__ result, int n)
{
    const int tid    = threadIdx.x;
    const int lane   = tid & 31;
    const int warp   = tid >> 5;
    const int idx    = blockIdx.x * NTH + tid;
    const int stride = gridDim.x * NTH;
    const int n4     = n >> 2;

    const float4* o4 = (const float4*)out;
    const float4* t4 = (const float4*)tgt;

    float sum = 0.0f;
    for (int i = idx; i < n4; i += stride) {
        float4 o = o4[i];
        float4 t = t4[i];
        sum += elem_val(o.x, t.x);
        sum += elem_val(o.y, t.y);
        sum += elem_val(o.z, t.z);
        sum += elem_val(o.w, t.w);
    }
    for (int i = (n4 << 2) + idx; i < n; i += stride)   // tail
        sum += elem_val(out[i], tgt[i]);

    // ---- block reduce (all shuffles in fully-active warps) ----
    #pragma unroll
    for (int off = 16; off > 0; off >>= 1)
        sum += __shfl_down_sync(0xFFFFFFFFu, sum, off);

    __shared__ float s_warp[NTH / 32];
    __shared__ bool  s_last;
    if (lane == 0) s_warp[warp] = sum;
    __syncthreads();

    if (warp == 0) {                      // full warp active
        float v = (lane < NTH / 32) ? s_warp[lane] : 0.0f;
        #pragma unroll
        for (int off = 16; off > 0; off >>= 1)
            v += __shfl_down_sync(0xFFFFFFFFu, v, off);
        if (lane == 0) {
            g_part[blockIdx.x] = v;
            __threadfence();                              // release partial
            unsigned int prev = atomicInc(&g_count, NBLK - 1u);  // wraps->0 on last
            s_last = (prev == NBLK - 1u);
        }
    }
    __syncthreads();

    if (s_last) {
        __threadfence();                  // acquire: order g_part reads after count
        // fixed-order deterministic reduce of all partials, fp64 accumulate
        double acc = 0.0;
        for (int i = tid; i < NBLK; i += NTH)
            acc += (double)g_part[i];

        #pragma unroll
        for (int off = 16; off > 0; off >>= 1)
            acc += __shfl_down_sync(0xFFFFFFFFu, acc, off);

        __shared__ double s_d[NTH / 32];
        if (lane == 0) s_d[warp] = acc;
        __syncthreads();

        if (warp == 0) {                  // full warp active
            double v = (lane < NTH / 32) ? s_d[lane] : 0.0;
            #pragma unroll
            for (int off = 16; off > 0; off >>= 1)
                v += __shfl_down_sync(0xFFFFFFFFu, v, off);
            if (lane == 0)
                result[0] = (float)(v / (double)n);
        }
    }
}

extern "C" void kernel_launch(void* const* d_in, const int* in_sizes, int n_in,
                              void* d_out, int out_size)
{
    const float* output = (const float*)d_in[0];
    const float* target = (const float*)d_in[1];
    const int n = in_sizes[0];

    loss_fused_kernel<<<NBLK, NTH>>>(output, target, (float*)d_out, n);
}